// round 11
// baseline (speedup 1.0000x reference)
#include <cuda_runtime.h>
#include <cuda_bf16.h>
#include <cstdint>

#define T  2048
#define E  1024
#define H  16
#define Dh 64
#define F  4096
#define EPS 1e-5f
#define N_QKV 3072
#define STAGES 4

// ---------------- scratch ----------------
__device__ __nv_bfloat16 g_Qh[H * T * Dh];
__device__ __nv_bfloat16 g_Ql[H * T * Dh];
__device__ __nv_bfloat16 g_Kh[H * T * Dh];
__device__ __nv_bfloat16 g_Kl[H * T * Dh];
__device__ __nv_bfloat16 g_Vh[H * T * Dh];
__device__ __nv_bfloat16 g_Vl[H * T * Dh];

__device__ __nv_bfloat16 g_xh[T * E],  g_xl[T * E];
__device__ __nv_bfloat16 g_Wh[E * N_QKV], g_Wl[E * N_QKV];
__device__ __nv_bfloat16 g_pwh[E * E], g_pwl[E * E];
__device__ __nv_bfloat16 g_w1h[E * F], g_w1l[E * F];
__device__ __nv_bfloat16 g_w2h[F * E], g_w2l[F * E];
__device__ __nv_bfloat16 g_ch[T * E],  g_cl[T * E];
__device__ __nv_bfloat16 g_hh[T * E],  g_hl[T * E];
__device__ __nv_bfloat16 g_fh[T * F],  g_fl[T * F];

__device__ float g_attn[T * E];
__device__ float g_h[T * E];
__device__ float g_ffn[T * E];

// ---------------- helpers ----------------
__device__ __forceinline__ uint32_t smem_u32(const void* p) {
    return (uint32_t)__cvta_generic_to_shared(p);
}
__device__ __forceinline__ void ldm_x4(uint32_t* r, uint32_t a) {
    asm volatile("ldmatrix.sync.aligned.m8n8.x4.shared.b16 {%0,%1,%2,%3},[%4];"
                 : "=r"(r[0]), "=r"(r[1]), "=r"(r[2]), "=r"(r[3]) : "r"(a));
}
__device__ __forceinline__ void ldm_x4t(uint32_t* r, uint32_t a) {
    asm volatile("ldmatrix.sync.aligned.m8n8.x4.trans.shared.b16 {%0,%1,%2,%3},[%4];"
                 : "=r"(r[0]), "=r"(r[1]), "=r"(r[2]), "=r"(r[3]) : "r"(a));
}
__device__ __forceinline__ void ldm_x2t(uint32_t& r0, uint32_t& r1, uint32_t a) {
    asm volatile("ldmatrix.sync.aligned.m8n8.x2.trans.shared.b16 {%0,%1},[%2];"
                 : "=r"(r0), "=r"(r1) : "r"(a));
}
__device__ __forceinline__ void mma16816(float* d, const uint32_t* a, const uint32_t* b) {
    asm volatile(
        "mma.sync.aligned.m16n8k16.row.col.f32.bf16.bf16.f32 "
        "{%0,%1,%2,%3},{%4,%5,%6,%7},{%8,%9},{%0,%1,%2,%3};"
        : "+f"(d[0]), "+f"(d[1]), "+f"(d[2]), "+f"(d[3])
        : "r"(a[0]), "r"(a[1]), "r"(a[2]), "r"(a[3]), "r"(b[0]), "r"(b[1]));
}
__device__ __forceinline__ uint32_t pack_b2(__nv_bfloat16 a, __nv_bfloat16 b) {
    __nv_bfloat162 t = __halves2bfloat162(a, b);
    return *reinterpret_cast<uint32_t*>(&t);
}
__device__ __forceinline__ void split4(float4 v, uint2& hi, uint2& lo) {
    float f[4] = {v.x, v.y, v.z, v.w};
    __nv_bfloat16 h[4], l[4];
    #pragma unroll
    for (int i = 0; i < 4; ++i) {
        h[i] = __float2bfloat16(f[i]);
        l[i] = __float2bfloat16(f[i] - __bfloat162float(h[i]));
    }
    hi.x = pack_b2(h[0], h[1]); hi.y = pack_b2(h[2], h[3]);
    lo.x = pack_b2(l[0], l[1]); lo.y = pack_b2(l[2], l[3]);
}
__device__ __forceinline__ void pack_hilo(float x, float y, uint32_t& hi, uint32_t& lo) {
    __nv_bfloat16 hx = __float2bfloat16(x), hy = __float2bfloat16(y);
    __nv_bfloat16 lx = __float2bfloat16(x - __bfloat162float(hx));
    __nv_bfloat16 ly = __float2bfloat16(y - __bfloat162float(hy));
    hi = pack_b2(hx, hy); lo = pack_b2(lx, ly);
}
__device__ __forceinline__ void cp16(void* dst, const void* src) {
    asm volatile("cp.async.cg.shared.global [%0],[%1],16;" :: "r"(smem_u32(dst)), "l"(src));
}
__device__ __forceinline__ void cp_commit() {
    asm volatile("cp.async.commit_group;" ::: "memory");
}
__device__ __forceinline__ void cp_wait0() {
    asm volatile("cp.async.wait_group 0;" ::: "memory");
}

// =====================================================================
// Conversion kernels
// =====================================================================
__global__ void conv_split(const float4* __restrict__ src,
                           uint2* __restrict__ hi, uint2* __restrict__ lo, int n4)
{
    const int i = blockIdx.x * blockDim.x + threadIdx.x;
    if (i < n4) {
        uint2 h, l;
        split4(src[i], h, l);
        hi[i] = h; lo[i] = l;
    }
}

__global__ void conv_qkvw(const float* __restrict__ wq,
                          const float* __restrict__ wk,
                          const float* __restrict__ wv)
{
    const int i = blockIdx.x * blockDim.x + threadIdx.x;
    if (i >= E * N_QKV / 2) return;
    const int e  = i / (N_QKV / 2);
    const int n  = (i % (N_QKV / 2)) * 2;
    const int which = n >> 10, head = (n >> 6) & 15, d = n & 63;
    const float* w = (which == 0 ? wq : which == 1 ? wk : wv);
    const size_t base = ((size_t)head * E + e) * Dh + d;
    uint32_t hi, lo;
    pack_hilo(w[base], w[base + 1], hi, lo);
    *reinterpret_cast<uint32_t*>(&g_Wh[(size_t)e * N_QKV + n]) = hi;
    *reinterpret_cast<uint32_t*>(&g_Wl[(size_t)e * N_QKV + n]) = lo;
}

// =====================================================================
// bf16x3 GEMM: 128x128 tile, BK=16, 4-stage cp.async pipeline,
// dynamic smem (82KB), ONE __syncthreads per k-tile, no reg staging.
// MODE 0: f32 out (+BIAS). MODE 1: bias+relu -> hi/lo. MODE 2: QKV scatter.
// =====================================================================
#define A_ST (128 * 24)         // elems per A stage (hi or lo)
#define B_ST (16 * 136)         // elems per B stage
#define GEMM_SMEM_BYTES ((2 * STAGES * A_ST + 2 * STAGES * B_ST) * 2)

template<int MODE, int BIAS>
__global__ void __launch_bounds__(256) gemm3(
    const __nv_bfloat16* __restrict__ Ah, const __nv_bfloat16* __restrict__ Al,
    const __nv_bfloat16* __restrict__ Bh, const __nv_bfloat16* __restrict__ Bl,
    const float* __restrict__ bias, float* __restrict__ Cf,
    __nv_bfloat16* __restrict__ Ch, __nv_bfloat16* __restrict__ Cl,
    int N, int K)
{
    extern __shared__ __align__(16) char smem_raw[];
    __nv_bfloat16* sAh = reinterpret_cast<__nv_bfloat16*>(smem_raw);
    __nv_bfloat16* sAl = sAh + STAGES * A_ST;
    __nv_bfloat16* sBh = sAl + STAGES * A_ST;
    __nv_bfloat16* sBl = sBh + STAGES * B_ST;

    const int tid  = threadIdx.x;
    const int lane = tid & 31;
    const int wid  = tid >> 5;
    const int wm   = wid >> 2;
    const int wn   = wid & 3;
    const int m0   = blockIdx.y * 128;
    const int n0   = blockIdx.x * 128;
    const int KT   = K >> 4;                 // BK = 16

    // cp.async mappings: one 16B chunk per array per thread per tile
    const int a_r = tid >> 1, a_c = (tid & 1) * 8;    // A: 128 rows x 2 chunks
    const int b_r = tid >> 4, b_c = (tid & 15) * 8;   // B: 16 rows x 16 chunks

    auto issue = [&](int kt) {
        const int st = kt & (STAGES - 1);
        const int k0 = kt << 4;
        const size_t aoff = (size_t)(m0 + a_r) * K + k0 + a_c;
        const size_t boff = (size_t)(k0 + b_r) * N + n0 + b_c;
        cp16(&sAh[(st * 128 + a_r) * 24 + a_c], Ah + aoff);
        cp16(&sAl[(st * 128 + a_r) * 24 + a_c], Al + aoff);
        cp16(&sBh[(st * 16 + b_r) * 136 + b_c], Bh + boff);
        cp16(&sBl[(st * 16 + b_r) * 136 + b_c], Bl + boff);
        cp_commit();
    };

    float acc[4][4][4] = {};

    #pragma unroll
    for (int s = 0; s < STAGES - 1; ++s) issue(s);

    const int ar = lane & 15;
    const int ac = (lane >> 4) * 8;

    for (int kt = 0; kt < KT; ++kt) {
        const int st = kt & (STAGES - 1);
        asm volatile("cp.async.wait_group %0;" :: "n"(STAGES - 2));
        __syncthreads();
        if (kt + STAGES - 1 < KT) issue(kt + STAGES - 1);

        uint32_t afh[4][4], afl[4][4], bfh[4][2], bfl[4][2];
        #pragma unroll
        for (int mt = 0; mt < 4; ++mt) {
            const int r = st * 128 + wm * 64 + mt * 16 + ar;
            ldm_x4(afh[mt], smem_u32(&sAh[r * 24 + ac]));
            ldm_x4(afl[mt], smem_u32(&sAl[r * 24 + ac]));
        }
        #pragma unroll
        for (int nt = 0; nt < 4; ++nt) {
            const int c = wn * 32 + nt * 8;
            ldm_x2t(bfh[nt][0], bfh[nt][1], smem_u32(&sBh[(st * 16 + ar) * 136 + c]));
            ldm_x2t(bfl[nt][0], bfl[nt][1], smem_u32(&sBl[(st * 16 + ar) * 136 + c]));
        }
        #pragma unroll
        for (int mt = 0; mt < 4; ++mt)
            #pragma unroll
            for (int nt = 0; nt < 4; ++nt) {
                mma16816(acc[mt][nt], afh[mt], bfh[nt]);
                mma16816(acc[mt][nt], afh[mt], bfl[nt]);
                mma16816(acc[mt][nt], afl[mt], bfh[nt]);
            }
    }

    // ---- epilogue
    #pragma unroll
    for (int mt = 0; mt < 4; ++mt) {
        const int m = m0 + wm * 64 + mt * 16 + (lane >> 2);
        #pragma unroll
        for (int nt = 0; nt < 4; ++nt) {
            const int n = n0 + wn * 32 + nt * 8 + (lane & 3) * 2;
            float v0 = acc[mt][nt][0], v1 = acc[mt][nt][1];
            float v2 = acc[mt][nt][2], v3 = acc[mt][nt][3];
            if (BIAS) { v0 += bias[n]; v1 += bias[n + 1]; v2 += bias[n]; v3 += bias[n + 1]; }
            if (MODE == 0) {
                *reinterpret_cast<float2*>(Cf + (size_t)m * N + n)       = make_float2(v0, v1);
                *reinterpret_cast<float2*>(Cf + (size_t)(m + 8) * N + n) = make_float2(v2, v3);
            } else if (MODE == 1) {
                v0 = fmaxf(v0, 0.f); v1 = fmaxf(v1, 0.f);
                v2 = fmaxf(v2, 0.f); v3 = fmaxf(v3, 0.f);
                uint32_t hi, lo;
                pack_hilo(v0, v1, hi, lo);
                *reinterpret_cast<uint32_t*>(&Ch[(size_t)m * N + n]) = hi;
                *reinterpret_cast<uint32_t*>(&Cl[(size_t)m * N + n]) = lo;
                pack_hilo(v2, v3, hi, lo);
                *reinterpret_cast<uint32_t*>(&Ch[(size_t)(m + 8) * N + n]) = hi;
                *reinterpret_cast<uint32_t*>(&Cl[(size_t)(m + 8) * N + n]) = lo;
            } else {
                const int w2 = n >> 10, h2 = (n >> 6) & 15, d2 = n & 63;
                if (w2 == 0) { v0 *= 0.125f; v1 *= 0.125f; v2 *= 0.125f; v3 *= 0.125f; }
                __nv_bfloat16* dh = (w2 == 0 ? g_Qh : w2 == 1 ? g_Kh : g_Vh);
                __nv_bfloat16* dl = (w2 == 0 ? g_Ql : w2 == 1 ? g_Kl : g_Vl);
                const size_t o0 = ((size_t)h2 * T + m) * Dh + d2;
                const size_t o1 = ((size_t)h2 * T + m + 8) * Dh + d2;
                uint32_t hi, lo;
                pack_hilo(v0, v1, hi, lo);
                *reinterpret_cast<uint32_t*>(&dh[o0]) = hi;
                *reinterpret_cast<uint32_t*>(&dl[o0]) = lo;
                pack_hilo(v2, v3, hi, lo);
                *reinterpret_cast<uint32_t*>(&dh[o1]) = hi;
                *reinterpret_cast<uint32_t*>(&dl[o1]) = lo;
            }
        }
    }
}

// =====================================================================
// Tensor-core flash attention (unchanged from R9)
// =====================================================================
__global__ void __launch_bounds__(128) attn_tc()
{
    __shared__ __align__(16) __nv_bfloat16 Kh_s[64][72];
    __shared__ __align__(16) __nv_bfloat16 Kl_s[64][72];
    __shared__ __align__(16) __nv_bfloat16 Vh_s[64][72];
    __shared__ __align__(16) __nv_bfloat16 Vl_s[64][72];

    const int tid  = threadIdx.x;
    const int lane = tid & 31;
    const int wid  = tid >> 5;
    const int qb   = (int)(gridDim.x - 1 - blockIdx.x) * 64;
    const int h    = blockIdx.y;
    const int mbase = qb + wid * 16;

    const __nv_bfloat16* Qh = g_Qh + (size_t)h * T * Dh;
    const __nv_bfloat16* Ql = g_Ql + (size_t)h * T * Dh;
    const __nv_bfloat16* Kh = g_Kh + (size_t)h * T * Dh;
    const __nv_bfloat16* Kl = g_Kl + (size_t)h * T * Dh;
    const __nv_bfloat16* Vh = g_Vh + (size_t)h * T * Dh;
    const __nv_bfloat16* Vl = g_Vl + (size_t)h * T * Dh;

    #pragma unroll
    for (int i = 0; i < 4; ++i) {
        const int idx = tid + i * 128;
        const int r = idx >> 3, c8 = idx & 7;
        cp16(&Kh_s[r][c8 * 8], Qh + (size_t)(qb + r) * Dh + c8 * 8);
        cp16(&Kl_s[r][c8 * 8], Ql + (size_t)(qb + r) * Dh + c8 * 8);
    }
    cp_commit(); cp_wait0();
    __syncthreads();

    uint32_t qfh[4][4], qfl[4][4];
    #pragma unroll
    for (int ks = 0; ks < 4; ++ks) {
        const int r = wid * 16 + (lane & 15);
        const int c = ks * 16 + (lane >> 4) * 8;
        ldm_x4(qfh[ks], smem_u32(&Kh_s[r][c]));
        ldm_x4(qfl[ks], smem_u32(&Kl_s[r][c]));
    }
    __syncthreads();

    float oacc[8][4] = {};
    float m0 = -1e30f, m1 = -1e30f, l0 = 0.f, l1 = 0.f;
    const int niter = qb / 64 + 1;

    for (int it = 0; it < niter; ++it) {
        const int kb = it * 64;

        #pragma unroll
        for (int i = 0; i < 4; ++i) {
            const int idx = tid + i * 128;
            const int r = idx >> 3, c8 = idx & 7;
            const size_t go = (size_t)(kb + r) * Dh + c8 * 8;
            cp16(&Kh_s[r][c8 * 8], Kh + go);
            cp16(&Kl_s[r][c8 * 8], Kl + go);
            cp16(&Vh_s[r][c8 * 8], Vh + go);
            cp16(&Vl_s[r][c8 * 8], Vl + go);
        }
        cp_commit(); cp_wait0();
        __syncthreads();

        float sacc[8][4] = {};
        #pragma unroll
        for (int ks = 0; ks < 4; ++ks) {
            #pragma unroll
            for (int jp = 0; jp < 4; ++jp) {
                uint32_t bh[4], bl[4];
                const int row = jp * 16 + (lane & 7) + ((lane >> 4) << 3);
                const int col = ks * 16 + (((lane >> 3) & 1) << 3);
                ldm_x4(bh, smem_u32(&Kh_s[row][col]));
                ldm_x4(bl, smem_u32(&Kl_s[row][col]));
                mma16816(sacc[2 * jp],     qfh[ks], bh);
                mma16816(sacc[2 * jp],     qfh[ks], bl);
                mma16816(sacc[2 * jp],     qfl[ks], bh);
                mma16816(sacc[2 * jp + 1], qfh[ks], bh + 2);
                mma16816(sacc[2 * jp + 1], qfh[ks], bl + 2);
                mma16816(sacc[2 * jp + 1], qfl[ks], bh + 2);
            }
        }

        if (kb + 63 > mbase) {
            const int row0 = mbase + (lane >> 2);
            const int row1 = row0 + 8;
            const int cb   = kb + ((lane & 3) << 1);
            #pragma unroll
            for (int nt = 0; nt < 8; ++nt) {
                const int c = cb + nt * 8;
                if (c     > row0) sacc[nt][0] = -1e30f;
                if (c + 1 > row0) sacc[nt][1] = -1e30f;
                if (c     > row1) sacc[nt][2] = -1e30f;
                if (c + 1 > row1) sacc[nt][3] = -1e30f;
            }
        }

        float t0 = -1e30f, t1 = -1e30f;
        #pragma unroll
        for (int nt = 0; nt < 8; ++nt) {
            t0 = fmaxf(t0, fmaxf(sacc[nt][0], sacc[nt][1]));
            t1 = fmaxf(t1, fmaxf(sacc[nt][2], sacc[nt][3]));
        }
        t0 = fmaxf(t0, __shfl_xor_sync(0xffffffffu, t0, 1));
        t0 = fmaxf(t0, __shfl_xor_sync(0xffffffffu, t0, 2));
        t1 = fmaxf(t1, __shfl_xor_sync(0xffffffffu, t1, 1));
        t1 = fmaxf(t1, __shfl_xor_sync(0xffffffffu, t1, 2));
        const float mn0 = fmaxf(m0, t0), mn1 = fmaxf(m1, t1);
        const float a0 = __expf(m0 - mn0), a1 = __expf(m1 - mn1);
        m0 = mn0; m1 = mn1;

        float sum0 = 0.f, sum1 = 0.f;
        #pragma unroll
        for (int nt = 0; nt < 8; ++nt) {
            sacc[nt][0] = __expf(sacc[nt][0] - mn0);
            sacc[nt][1] = __expf(sacc[nt][1] - mn0);
            sacc[nt][2] = __expf(sacc[nt][2] - mn1);
            sacc[nt][3] = __expf(sacc[nt][3] - mn1);
            sum0 += sacc[nt][0] + sacc[nt][1];
            sum1 += sacc[nt][2] + sacc[nt][3];
        }
        sum0 += __shfl_xor_sync(0xffffffffu, sum0, 1);
        sum0 += __shfl_xor_sync(0xffffffffu, sum0, 2);
        sum1 += __shfl_xor_sync(0xffffffffu, sum1, 1);
        sum1 += __shfl_xor_sync(0xffffffffu, sum1, 2);
        l0 = l0 * a0 + sum0;
        l1 = l1 * a1 + sum1;

        #pragma unroll
        for (int nt = 0; nt < 8; ++nt) {
            oacc[nt][0] *= a0; oacc[nt][1] *= a0;
            oacc[nt][2] *= a1; oacc[nt][3] *= a1;
        }

        uint32_t pfh[4][4], pfl[4][4];
        #pragma unroll
        for (int ks = 0; ks < 4; ++ks) {
            pack_hilo(sacc[2 * ks][0],     sacc[2 * ks][1],     pfh[ks][0], pfl[ks][0]);
            pack_hilo(sacc[2 * ks][2],     sacc[2 * ks][3],     pfh[ks][1], pfl[ks][1]);
            pack_hilo(sacc[2 * ks + 1][0], sacc[2 * ks + 1][1], pfh[ks][2], pfl[ks][2]);
            pack_hilo(sacc[2 * ks + 1][2], sacc[2 * ks + 1][3], pfh[ks][3], pfl[ks][3]);
        }

        #pragma unroll
        for (int ks = 0; ks < 4; ++ks) {
            #pragma unroll
            for (int jp = 0; jp < 4; ++jp) {
                uint32_t vh[4], vl[4];
                const int row = ks * 16 + (lane & 15);
                const int col = jp * 16 + ((lane >> 4) << 3);
                ldm_x4t(vh, smem_u32(&Vh_s[row][col]));
                ldm_x4t(vl, smem_u32(&Vl_s[row][col]));
                mma16816(oacc[2 * jp],     pfh[ks], vh);
                mma16816(oacc[2 * jp],     pfl[ks], vh);
                mma16816(oacc[2 * jp],     pfh[ks], vl);
                mma16816(oacc[2 * jp + 1], pfh[ks], vh + 2);
                mma16816(oacc[2 * jp + 1], pfl[ks], vh + 2);
                mma16816(oacc[2 * jp + 1], pfh[ks], vl + 2);
            }
        }
        __syncthreads();
    }

    const float i0 = 1.0f / l0, i1 = 1.0f / l1;
    const int r0 = mbase + (lane >> 2);
    const int cb = h * Dh + ((lane & 3) << 1);
    #pragma unroll
    for (int nt = 0; nt < 8; ++nt) {
        const int c = cb + nt * 8;
        uint32_t hi, lo;
        pack_hilo(oacc[nt][0] * i0, oacc[nt][1] * i0, hi, lo);
        *reinterpret_cast<uint32_t*>(&g_ch[(size_t)r0 * E + c]) = hi;
        *reinterpret_cast<uint32_t*>(&g_cl[(size_t)r0 * E + c]) = lo;
        pack_hilo(oacc[nt][2] * i1, oacc[nt][3] * i1, hi, lo);
        *reinterpret_cast<uint32_t*>(&g_ch[(size_t)(r0 + 8) * E + c]) = hi;
        *reinterpret_cast<uint32_t*>(&g_cl[(size_t)(r0 + 8) * E + c]) = lo;
    }
}

// =====================================================================
// residual + LayerNorm (optional hi/lo bf16 output)
// =====================================================================
template<int WB>
__global__ void ln_kernel(const float* __restrict__ a, const float* __restrict__ b,
                          const float* __restrict__ gamma, const float* __restrict__ beta,
                          float* __restrict__ out,
                          __nv_bfloat16* __restrict__ oh, __nv_bfloat16* __restrict__ ol)
{
    const int row = blockIdx.x;
    const int tid = threadIdx.x;

    const float4 va = *reinterpret_cast<const float4*>(a + (size_t)row * E + tid * 4);
    const float4 vb = *reinterpret_cast<const float4*>(b + (size_t)row * E + tid * 4);
    float4 v = make_float4(va.x + vb.x, va.y + vb.y, va.z + vb.z, va.w + vb.w);

    float s  = v.x + v.y + v.z + v.w;
    float s2 = v.x * v.x + v.y * v.y + v.z * v.z + v.w * v.w;

    __shared__ float shs[32], shq[32];
    #pragma unroll
    for (int o = 16; o; o >>= 1) {
        s  += __shfl_xor_sync(0xffffffffu, s, o);
        s2 += __shfl_xor_sync(0xffffffffu, s2, o);
    }
    const int warp = tid >> 5, lane = tid & 31;
    if (lane == 0) { shs[warp] = s; shq[warp] = s2; }
    __syncthreads();
    if (tid < 32) {
        s  = (tid < 8) ? shs[tid] : 0.0f;
        s2 = (tid < 8) ? shq[tid] : 0.0f;
        #pragma unroll
        for (int o = 4; o; o >>= 1) {
            s  += __shfl_xor_sync(0xffffffffu, s, o);
            s2 += __shfl_xor_sync(0xffffffffu, s2, o);
        }
        if (tid == 0) { shs[0] = s; shq[0] = s2; }
    }
    __syncthreads();
    s = shs[0]; s2 = shq[0];

    const float mean = s * (1.0f / E);
    const float var  = s2 * (1.0f / E) - mean * mean;
    const float inv  = rsqrtf(var + EPS);
    const float g    = gamma[0];
    const float4 bt  = *reinterpret_cast<const float4*>(beta + tid * 4);

    float4 res;
    res.x = g * (v.x - mean) * inv + bt.x;
    res.y = g * (v.y - mean) * inv + bt.y;
    res.z = g * (v.z - mean) * inv + bt.z;
    res.w = g * (v.w - mean) * inv + bt.w;
    *reinterpret_cast<float4*>(out + (size_t)row * E + tid * 4) = res;

    if (WB) {
        uint2 hi, lo;
        split4(res, hi, lo);
        *reinterpret_cast<uint2*>(&oh[(size_t)row * E + tid * 4]) = hi;
        *reinterpret_cast<uint2*>(&ol[(size_t)row * E + tid * 4]) = lo;
    }
}

// ---------------- launch ----------------
extern "C" void kernel_launch(void* const* d_in, const int* in_sizes, int n_in,
                              void* d_out, int out_size)
{
    const float* x      = (const float*)d_in[0];
    const float* wq     = (const float*)d_in[1];
    const float* wk     = (const float*)d_in[2];
    const float* wv     = (const float*)d_in[3];
    const float* pool_w = (const float*)d_in[4];
    const float* l1_w   = (const float*)d_in[5];
    const float* l1_b   = (const float*)d_in[6];
    const float* l2_w   = (const float*)d_in[7];
    const float* l2_b   = (const float*)d_in[8];
    const float* gamma  = (const float*)d_in[9];
    const float* beta   = (const float*)d_in[10];
    float* out = (float*)d_out;

    __nv_bfloat16 *pxh, *pxl, *pWh, *pWl, *ppwh, *ppwl, *pw1h, *pw1l, *pw2h, *pw2l;
    __nv_bfloat16 *pch, *pcl, *phh, *phl, *pfh, *pfl;
    float *pA, *pH, *pN;
    cudaGetSymbolAddress((void**)&pxh,  g_xh);  cudaGetSymbolAddress((void**)&pxl,  g_xl);
    cudaGetSymbolAddress((void**)&pWh,  g_Wh);  cudaGetSymbolAddress((void**)&pWl,  g_Wl);
    cudaGetSymbolAddress((void**)&ppwh, g_pwh); cudaGetSymbolAddress((void**)&ppwl, g_pwl);
    cudaGetSymbolAddress((void**)&pw1h, g_w1h); cudaGetSymbolAddress((void**)&pw1l, g_w1l);
    cudaGetSymbolAddress((void**)&pw2h, g_w2h); cudaGetSymbolAddress((void**)&pw2l, g_w2l);
    cudaGetSymbolAddress((void**)&pch,  g_ch);  cudaGetSymbolAddress((void**)&pcl,  g_cl);
    cudaGetSymbolAddress((void**)&phh,  g_hh);  cudaGetSymbolAddress((void**)&phl,  g_hl);
    cudaGetSymbolAddress((void**)&pfh,  g_fh);  cudaGetSymbolAddress((void**)&pfl,  g_fl);
    cudaGetSymbolAddress((void**)&pA,   g_attn);
    cudaGetSymbolAddress((void**)&pH,   g_h);
    cudaGetSymbolAddress((void**)&pN,   g_ffn);

    // opt-in to 82KB dynamic smem (idempotent host-side attribute)
    cudaFuncSetAttribute(gemm3<2, 0>, cudaFuncAttributeMaxDynamicSharedMemorySize, GEMM_SMEM_BYTES);
    cudaFuncSetAttribute(gemm3<0, 0>, cudaFuncAttributeMaxDynamicSharedMemorySize, GEMM_SMEM_BYTES);
    cudaFuncSetAttribute(gemm3<1, 1>, cudaFuncAttributeMaxDynamicSharedMemorySize, GEMM_SMEM_BYTES);
    cudaFuncSetAttribute(gemm3<0, 1>, cudaFuncAttributeMaxDynamicSharedMemorySize, GEMM_SMEM_BYTES);

    conv_split<<<(T * E / 4 + 255) / 256, 256>>>((const float4*)x,      (uint2*)pxh,  (uint2*)pxl,  T * E / 4);
    conv_qkvw <<<(E * N_QKV / 2 + 255) / 256, 256>>>(wq, wk, wv);
    conv_split<<<(E * E / 4 + 255) / 256, 256>>>((const float4*)pool_w, (uint2*)ppwh, (uint2*)ppwl, E * E / 4);
    conv_split<<<(E * F / 4 + 255) / 256, 256>>>((const float4*)l1_w,   (uint2*)pw1h, (uint2*)pw1l, E * F / 4);
    conv_split<<<(F * E / 4 + 255) / 256, 256>>>((const float4*)l2_w,   (uint2*)pw2h, (uint2*)pw2l, F * E / 4);

    gemm3<2, 0><<<dim3(N_QKV / 128, T / 128), 256, GEMM_SMEM_BYTES>>>(
        pxh, pxl, pWh, pWl, nullptr, nullptr, nullptr, nullptr, N_QKV, E);
    attn_tc<<<dim3(T / 64, H), 128>>>();
    gemm3<0, 0><<<dim3(E / 128, T / 128), 256, GEMM_SMEM_BYTES>>>(
        pch, pcl, ppwh, ppwl, nullptr, pA, nullptr, nullptr, E, E);
    ln_kernel<1><<<T, 256>>>(x, pA, gamma, beta, pH, phh, phl);
    gemm3<1, 1><<<dim3(F / 128, T / 128), 256, GEMM_SMEM_BYTES>>>(
        phh, phl, pw1h, pw1l, l1_b, nullptr, pfh, pfl, F, E);
    gemm3<0, 1><<<dim3(E / 128, T / 128), 256, GEMM_SMEM_BYTES>>>(
        pfh, pfl, pw2h, pw2l, l2_b, pN, nullptr, nullptr, E, F);
    ln_kernel<0><<<T, 256>>>(pH, pN, gamma, beta, out, nullptr, nullptr);
}

// round 15
// speedup vs baseline: 1.9194x; 1.9194x over previous
#include <cuda_runtime.h>
#include <cuda_bf16.h>
#include <cuda_fp16.h>
#include <cstdint>

#define T  2048
#define E  1024
#define H  16
#define Dh 64
#define F  4096
#define EPS 1e-5f
#define N_QKV 3072

typedef __nv_bfloat16 bf16;

// ---------------- scratch ----------------
// attention operands stay bf16 hi/lo (proven accurate path)
__device__ bf16 g_Qh[H * T * Dh];
__device__ bf16 g_Ql[H * T * Dh];
__device__ bf16 g_Kh[H * T * Dh];
__device__ bf16 g_Kl[H * T * Dh];
__device__ bf16 g_Vh[H * T * Dh];
__device__ bf16 g_Vl[H * T * Dh];

// fp16 GEMM operands
__device__ __half g_x[T * E];            // x (A of QKV gemm)
__device__ __half g_W[E * N_QKV];        // gathered qkv weights [K=E][N=3072]
__device__ __half g_pw[E * E];           // pool_w  [K=E][N=E]
__device__ __half g_w1[E * F];           // l1_w    [K=E][N=F]
__device__ __half g_w2[F * E];           // l2_w    [K=F][N=E]
__device__ __half g_c[T * E];            // attention concat (A of pool)
__device__ __half g_hh[T * E];           // ln1 out (A of ffn1)
__device__ __half g_f[T * F];            // ffn1 out (A of ffn2)

__device__ float g_attn[T * E];
__device__ float g_h[T * E];
__device__ float g_ffn[T * E];

// ---------------- helpers ----------------
__device__ __forceinline__ uint32_t smem_u32(const void* p) {
    return (uint32_t)__cvta_generic_to_shared(p);
}
__device__ __forceinline__ uint32_t pack_b2(bf16 a, bf16 b) {
    __nv_bfloat162 t = __halves2bfloat162(a, b);
    return *reinterpret_cast<uint32_t*>(&t);
}
__device__ __forceinline__ void pack_hilo(float x, float y, uint32_t& hi, uint32_t& lo) {
    bf16 hx = __float2bfloat16(x), hy = __float2bfloat16(y);
    bf16 lx = __float2bfloat16(x - __bfloat162float(hx));
    bf16 ly = __float2bfloat16(y - __bfloat162float(hy));
    hi = pack_b2(hx, hy); lo = pack_b2(lx, ly);
}
__device__ __forceinline__ uint32_t packh2(float a, float b) {
    __half2 h = __floats2half2_rn(a, b);
    return *reinterpret_cast<uint32_t*>(&h);
}
__device__ __forceinline__ void cp16(void* dst, const void* src) {
    asm volatile("cp.async.cg.shared.global [%0],[%1],16;" :: "r"(smem_u32(dst)), "l"(src));
}
__device__ __forceinline__ void cp_commit() {
    asm volatile("cp.async.commit_group;" ::: "memory");
}
__device__ __forceinline__ void cp_wait0() {
    asm volatile("cp.async.wait_group 0;" ::: "memory");
}
__device__ __forceinline__ void ldm_x4(uint32_t* r, uint32_t a) {
    asm volatile("ldmatrix.sync.aligned.m8n8.x4.shared.b16 {%0,%1,%2,%3},[%4];"
                 : "=r"(r[0]), "=r"(r[1]), "=r"(r[2]), "=r"(r[3]) : "r"(a));
}
__device__ __forceinline__ void ldm_x4t(uint32_t* r, uint32_t a) {
    asm volatile("ldmatrix.sync.aligned.m8n8.x4.trans.shared.b16 {%0,%1,%2,%3},[%4];"
                 : "=r"(r[0]), "=r"(r[1]), "=r"(r[2]), "=r"(r[3]) : "r"(a));
}
__device__ __forceinline__ void ldm_x2t(uint32_t& r0, uint32_t& r1, uint32_t a) {
    asm volatile("ldmatrix.sync.aligned.m8n8.x2.trans.shared.b16 {%0,%1},[%2];"
                 : "=r"(r0), "=r"(r1) : "r"(a));
}
// bf16 mma (attention)
__device__ __forceinline__ void mma16816(float* d, const uint32_t* a, const uint32_t* b) {
    asm volatile(
        "mma.sync.aligned.m16n8k16.row.col.f32.bf16.bf16.f32 "
        "{%0,%1,%2,%3},{%4,%5,%6,%7},{%8,%9},{%0,%1,%2,%3};"
        : "+f"(d[0]), "+f"(d[1]), "+f"(d[2]), "+f"(d[3])
        : "r"(a[0]), "r"(a[1]), "r"(a[2]), "r"(a[3]), "r"(b[0]), "r"(b[1]));
}
// fp16 mma (GEMMs)
__device__ __forceinline__ void mma16816h(float* d, const uint32_t* a, const uint32_t* b) {
    asm volatile(
        "mma.sync.aligned.m16n8k16.row.col.f32.f16.f16.f32 "
        "{%0,%1,%2,%3},{%4,%5,%6,%7},{%8,%9},{%0,%1,%2,%3};"
        : "+f"(d[0]), "+f"(d[1]), "+f"(d[2]), "+f"(d[3])
        : "r"(a[0]), "r"(a[1]), "r"(a[2]), "r"(a[3]), "r"(b[0]), "r"(b[1]));
}

// =====================================================================
// Conversion kernels (fp32 -> fp16)
// =====================================================================
__global__ void conv_h(const float4* __restrict__ src, uint2* __restrict__ dst, int n4)
{
    const int i = blockIdx.x * blockDim.x + threadIdx.x;
    if (i < n4) {
        const float4 v = src[i];
        dst[i] = make_uint2(packh2(v.x, v.y), packh2(v.z, v.w));
    }
}

// gather wq/wk/wv[h][e][d] -> g_W[e][which*1024 + head*64 + d] fp16
__global__ void conv_qkvw_h(const float* __restrict__ wq,
                            const float* __restrict__ wk,
                            const float* __restrict__ wv)
{
    const int i = blockIdx.x * blockDim.x + threadIdx.x;
    if (i >= E * N_QKV / 2) return;
    const int e = i / (N_QKV / 2);
    const int n = (i % (N_QKV / 2)) * 2;
    const int which = n >> 10, head = (n >> 6) & 15, d = n & 63;
    const float* w = (which == 0 ? wq : which == 1 ? wk : wv);
    const size_t base = ((size_t)head * E + e) * Dh + d;
    *reinterpret_cast<uint32_t*>(&g_W[(size_t)e * N_QKV + n]) = packh2(w[base], w[base + 1]);
}

// =====================================================================
// fp16 single-term GEMM: 128x128 tile, BK=32, register-staged double
// store (R4 skeleton), 256 thr (8 warps = 2m x 4n), 32 HMMA/tile.
// MODE 0: f32 out (+BIAS). MODE 1: bias+relu -> fp16 out.
// MODE 2: QKV scatter -> bf16 hi/lo Q(scaled)/K/V.
// =====================================================================
template<int MODE, int BIAS>
__global__ void __launch_bounds__(256) gemm_h16(
    const __half* __restrict__ A, const __half* __restrict__ B,
    const float* __restrict__ bias, float* __restrict__ Cf,
    __half* __restrict__ Ch, int N, int K)
{
    __shared__ __align__(16) __half As[2][128][24];   // [slab][row][16 k + pad]
    __shared__ __align__(16) __half Bs[2][16][136];   // [slab][k][128 n + pad]

    const int tid  = threadIdx.x;
    const int lane = tid & 31;
    const int wid  = tid >> 5;
    const int wm   = wid >> 2;
    const int wn   = wid & 3;
    const int m0   = blockIdx.y * 128;
    const int n0   = blockIdx.x * 128;
    const int KT   = K >> 5;                 // BK = 32

    uint4 a_reg[2], b_reg[2];

    auto load_tile = [&](int kt) {
        const int k0 = kt << 5;
        #pragma unroll
        for (int i = 0; i < 2; ++i) {
            const int idx = tid + i * 256;            // 0..511
            const int row = idx >> 2, cc = (idx & 3) * 8;
            a_reg[i] = *reinterpret_cast<const uint4*>(A + (size_t)(m0 + row) * K + k0 + cc);
        }
        #pragma unroll
        for (int i = 0; i < 2; ++i) {
            const int idx = tid + i * 256;
            const int kr = idx >> 4, cc = (idx & 15) * 8;
            b_reg[i] = *reinterpret_cast<const uint4*>(B + (size_t)(k0 + kr) * N + n0 + cc);
        }
    };
    auto store_tile = [&]() {
        #pragma unroll
        for (int i = 0; i < 2; ++i) {
            const int idx = tid + i * 256;
            const int row = idx >> 2, cc = (idx & 3) * 8;
            const int slab = cc >> 4, kk = cc & 15;
            *reinterpret_cast<uint4*>(&As[slab][row][kk]) = a_reg[i];
        }
        #pragma unroll
        for (int i = 0; i < 2; ++i) {
            const int idx = tid + i * 256;
            const int kr = idx >> 4, cc = (idx & 15) * 8;
            const int slab = kr >> 4, r = kr & 15;
            *reinterpret_cast<uint4*>(&Bs[slab][r][cc]) = b_reg[i];
        }
    };

    float acc[4][4][4] = {};
    load_tile(0);
    store_tile();
    __syncthreads();

    const int ar = lane & 15;
    const int ac = (lane >> 4) * 8;

    for (int kt = 0; kt < KT; ++kt) {
        if (kt + 1 < KT) load_tile(kt + 1);

        #pragma unroll
        for (int slab = 0; slab < 2; ++slab) {
            uint32_t af[4][4], bf[4][2];
            #pragma unroll
            for (int mt = 0; mt < 4; ++mt)
                ldm_x4(af[mt], smem_u32(&As[slab][wm * 64 + mt * 16 + ar][ac]));
            #pragma unroll
            for (int nt = 0; nt < 4; ++nt)
                ldm_x2t(bf[nt][0], bf[nt][1], smem_u32(&Bs[slab][ar][wn * 32 + nt * 8]));
            #pragma unroll
            for (int mt = 0; mt < 4; ++mt)
                #pragma unroll
                for (int nt = 0; nt < 4; ++nt)
                    mma16816h(acc[mt][nt], af[mt], bf[nt]);
        }
        __syncthreads();
        if (kt + 1 < KT) {
            store_tile();
            __syncthreads();
        }
    }

    // ---- epilogue (R4 thread mapping)
    #pragma unroll
    for (int mt = 0; mt < 4; ++mt) {
        const int m = m0 + wm * 64 + mt * 16 + (lane >> 2);
        #pragma unroll
        for (int nt = 0; nt < 4; ++nt) {
            const int n = n0 + wn * 32 + nt * 8 + (lane & 3) * 2;
            float v0 = acc[mt][nt][0], v1 = acc[mt][nt][1];
            float v2 = acc[mt][nt][2], v3 = acc[mt][nt][3];
            if (BIAS) { v0 += bias[n]; v1 += bias[n + 1]; v2 += bias[n]; v3 += bias[n + 1]; }
            if (MODE == 0) {
                *reinterpret_cast<float2*>(Cf + (size_t)m * N + n)       = make_float2(v0, v1);
                *reinterpret_cast<float2*>(Cf + (size_t)(m + 8) * N + n) = make_float2(v2, v3);
            } else if (MODE == 1) {
                v0 = fmaxf(v0, 0.f); v1 = fmaxf(v1, 0.f);
                v2 = fmaxf(v2, 0.f); v3 = fmaxf(v3, 0.f);
                *reinterpret_cast<uint32_t*>(&Ch[(size_t)m * N + n])       = packh2(v0, v1);
                *reinterpret_cast<uint32_t*>(&Ch[(size_t)(m + 8) * N + n]) = packh2(v2, v3);
            } else {   // MODE 2: QKV scatter to bf16 hi/lo
                const int w2 = n >> 10, h2 = (n >> 6) & 15, d2 = n & 63;
                if (w2 == 0) { v0 *= 0.125f; v1 *= 0.125f; v2 *= 0.125f; v3 *= 0.125f; }
                bf16* dh = (w2 == 0 ? g_Qh : w2 == 1 ? g_Kh : g_Vh);
                bf16* dl = (w2 == 0 ? g_Ql : w2 == 1 ? g_Kl : g_Vl);
                const size_t o0 = ((size_t)h2 * T + m) * Dh + d2;
                const size_t o1 = ((size_t)h2 * T + m + 8) * Dh + d2;
                uint32_t hi, lo;
                pack_hilo(v0, v1, hi, lo);
                *reinterpret_cast<uint32_t*>(&dh[o0]) = hi;
                *reinterpret_cast<uint32_t*>(&dl[o0]) = lo;
                pack_hilo(v2, v3, hi, lo);
                *reinterpret_cast<uint32_t*>(&dh[o1]) = hi;
                *reinterpret_cast<uint32_t*>(&dl[o1]) = lo;
            }
        }
    }
}

// =====================================================================
// Tensor-core flash attention (R9 bf16x3; epilogue emits fp16 concat)
// =====================================================================
__global__ void __launch_bounds__(128) attn_tc()
{
    __shared__ __align__(16) bf16 Kh_s[64][72];
    __shared__ __align__(16) bf16 Kl_s[64][72];
    __shared__ __align__(16) bf16 Vh_s[64][72];
    __shared__ __align__(16) bf16 Vl_s[64][72];

    const int tid  = threadIdx.x;
    const int lane = tid & 31;
    const int wid  = tid >> 5;
    const int qb   = (int)(gridDim.x - 1 - blockIdx.x) * 64;
    const int h    = blockIdx.y;
    const int mbase = qb + wid * 16;

    const bf16* Qh = g_Qh + (size_t)h * T * Dh;
    const bf16* Ql = g_Ql + (size_t)h * T * Dh;
    const bf16* Kh = g_Kh + (size_t)h * T * Dh;
    const bf16* Kl = g_Kl + (size_t)h * T * Dh;
    const bf16* Vh = g_Vh + (size_t)h * T * Dh;
    const bf16* Vl = g_Vl + (size_t)h * T * Dh;

    #pragma unroll
    for (int i = 0; i < 4; ++i) {
        const int idx = tid + i * 128;
        const int r = idx >> 3, c8 = idx & 7;
        cp16(&Kh_s[r][c8 * 8], Qh + (size_t)(qb + r) * Dh + c8 * 8);
        cp16(&Kl_s[r][c8 * 8], Ql + (size_t)(qb + r) * Dh + c8 * 8);
    }
    cp_commit(); cp_wait0();
    __syncthreads();

    uint32_t qfh[4][4], qfl[4][4];
    #pragma unroll
    for (int ks = 0; ks < 4; ++ks) {
        const int r = wid * 16 + (lane & 15);
        const int c = ks * 16 + (lane >> 4) * 8;
        ldm_x4(qfh[ks], smem_u32(&Kh_s[r][c]));
        ldm_x4(qfl[ks], smem_u32(&Kl_s[r][c]));
    }
    __syncthreads();

    float oacc[8][4] = {};
    float m0 = -1e30f, m1 = -1e30f, l0 = 0.f, l1 = 0.f;
    const int niter = qb / 64 + 1;

    for (int it = 0; it < niter; ++it) {
        const int kb = it * 64;

        #pragma unroll
        for (int i = 0; i < 4; ++i) {
            const int idx = tid + i * 128;
            const int r = idx >> 3, c8 = idx & 7;
            const size_t go = (size_t)(kb + r) * Dh + c8 * 8;
            cp16(&Kh_s[r][c8 * 8], Kh + go);
            cp16(&Kl_s[r][c8 * 8], Kl + go);
            cp16(&Vh_s[r][c8 * 8], Vh + go);
            cp16(&Vl_s[r][c8 * 8], Vl + go);
        }
        cp_commit(); cp_wait0();
        __syncthreads();

        float sacc[8][4] = {};
        #pragma unroll
        for (int ks = 0; ks < 4; ++ks) {
            #pragma unroll
            for (int jp = 0; jp < 4; ++jp) {
                uint32_t bh[4], bl[4];
                const int row = jp * 16 + (lane & 7) + ((lane >> 4) << 3);
                const int col = ks * 16 + (((lane >> 3) & 1) << 3);
                ldm_x4(bh, smem_u32(&Kh_s[row][col]));
                ldm_x4(bl, smem_u32(&Kl_s[row][col]));
                mma16816(sacc[2 * jp],     qfh[ks], bh);
                mma16816(sacc[2 * jp],     qfh[ks], bl);
                mma16816(sacc[2 * jp],     qfl[ks], bh);
                mma16816(sacc[2 * jp + 1], qfh[ks], bh + 2);
                mma16816(sacc[2 * jp + 1], qfh[ks], bl + 2);
                mma16816(sacc[2 * jp + 1], qfl[ks], bh + 2);
            }
        }

        if (kb + 63 > mbase) {
            const int row0 = mbase + (lane >> 2);
            const int row1 = row0 + 8;
            const int cb   = kb + ((lane & 3) << 1);
            #pragma unroll
            for (int nt = 0; nt < 8; ++nt) {
                const int c = cb + nt * 8;
                if (c     > row0) sacc[nt][0] = -1e30f;
                if (c + 1 > row0) sacc[nt][1] = -1e30f;
                if (c     > row1) sacc[nt][2] = -1e30f;
                if (c + 1 > row1) sacc[nt][3] = -1e30f;
            }
        }

        float t0 = -1e30f, t1 = -1e30f;
        #pragma unroll
        for (int nt = 0; nt < 8; ++nt) {
            t0 = fmaxf(t0, fmaxf(sacc[nt][0], sacc[nt][1]));
            t1 = fmaxf(t1, fmaxf(sacc[nt][2], sacc[nt][3]));
        }
        t0 = fmaxf(t0, __shfl_xor_sync(0xffffffffu, t0, 1));
        t0 = fmaxf(t0, __shfl_xor_sync(0xffffffffu, t0, 2));
        t1 = fmaxf(t1, __shfl_xor_sync(0xffffffffu, t1, 1));
        t1 = fmaxf(t1, __shfl_xor_sync(0xffffffffu, t1, 2));
        const float mn0 = fmaxf(m0, t0), mn1 = fmaxf(m1, t1);
        const float a0 = __expf(m0 - mn0), a1 = __expf(m1 - mn1);
        m0 = mn0; m1 = mn1;

        float sum0 = 0.f, sum1 = 0.f;
        #pragma unroll
        for (int nt = 0; nt < 8; ++nt) {
            sacc[nt][0] = __expf(sacc[nt][0] - mn0);
            sacc[nt][1] = __expf(sacc[nt][1] - mn0);
            sacc[nt][2] = __expf(sacc[nt][2] - mn1);
            sacc[nt][3] = __expf(sacc[nt][3] - mn1);
            sum0 += sacc[nt][0] + sacc[nt][1];
            sum1 += sacc[nt][2] + sacc[nt][3];
        }
        sum0 += __shfl_xor_sync(0xffffffffu, sum0, 1);
        sum0 += __shfl_xor_sync(0xffffffffu, sum0, 2);
        sum1 += __shfl_xor_sync(0xffffffffu, sum1, 1);
        sum1 += __shfl_xor_sync(0xffffffffu, sum1, 2);
        l0 = l0 * a0 + sum0;
        l1 = l1 * a1 + sum1;

        #pragma unroll
        for (int nt = 0; nt < 8; ++nt) {
            oacc[nt][0] *= a0; oacc[nt][1] *= a0;
            oacc[nt][2] *= a1; oacc[nt][3] *= a1;
        }

        uint32_t pfh[4][4], pfl[4][4];
        #pragma unroll
        for (int ks = 0; ks < 4; ++ks) {
            pack_hilo(sacc[2 * ks][0],     sacc[2 * ks][1],     pfh[ks][0], pfl[ks][0]);
            pack_hilo(sacc[2 * ks][2],     sacc[2 * ks][3],     pfh[ks][1], pfl[ks][1]);
            pack_hilo(sacc[2 * ks + 1][0], sacc[2 * ks + 1][1], pfh[ks][2], pfl[ks][2]);
            pack_hilo(sacc[2 * ks + 1][2], sacc[2 * ks + 1][3], pfh[ks][3], pfl[ks][3]);
        }

        #pragma unroll
        for (int ks = 0; ks < 4; ++ks) {
            #pragma unroll
            for (int jp = 0; jp < 4; ++jp) {
                uint32_t vh[4], vl[4];
                const int row = ks * 16 + (lane & 15);
                const int col = jp * 16 + ((lane >> 4) << 3);
                ldm_x4t(vh, smem_u32(&Vh_s[row][col]));
                ldm_x4t(vl, smem_u32(&Vl_s[row][col]));
                mma16816(oacc[2 * jp],     pfh[ks], vh);
                mma16816(oacc[2 * jp],     pfl[ks], vh);
                mma16816(oacc[2 * jp],     pfh[ks], vl);
                mma16816(oacc[2 * jp + 1], pfh[ks], vh + 2);
                mma16816(oacc[2 * jp + 1], pfl[ks], vh + 2);
                mma16816(oacc[2 * jp + 1], pfh[ks], vl + 2);
            }
        }
        __syncthreads();
    }

    // epilogue: fp16 concat (feeds fp16 pool GEMM)
    const float i0 = 1.0f / l0, i1 = 1.0f / l1;
    const int r0 = mbase + (lane >> 2);
    const int cb = h * Dh + ((lane & 3) << 1);
    #pragma unroll
    for (int nt = 0; nt < 8; ++nt) {
        const int c = cb + nt * 8;
        *reinterpret_cast<uint32_t*>(&g_c[(size_t)r0 * E + c]) =
            packh2(oacc[nt][0] * i0, oacc[nt][1] * i0);
        *reinterpret_cast<uint32_t*>(&g_c[(size_t)(r0 + 8) * E + c]) =
            packh2(oacc[nt][2] * i1, oacc[nt][3] * i1);
    }
}

// =====================================================================
// residual + LayerNorm (optional fp16 output)
// =====================================================================
template<int WB>
__global__ void ln_kernel(const float* __restrict__ a, const float* __restrict__ b,
                          const float* __restrict__ gamma, const float* __restrict__ beta,
                          float* __restrict__ out, __half* __restrict__ oh)
{
    const int row = blockIdx.x;
    const int tid = threadIdx.x;

    const float4 va = *reinterpret_cast<const float4*>(a + (size_t)row * E + tid * 4);
    const float4 vb = *reinterpret_cast<const float4*>(b + (size_t)row * E + tid * 4);
    float4 v = make_float4(va.x + vb.x, va.y + vb.y, va.z + vb.z, va.w + vb.w);

    float s  = v.x + v.y + v.z + v.w;
    float s2 = v.x * v.x + v.y * v.y + v.z * v.z + v.w * v.w;

    __shared__ float shs[32], shq[32];
    #pragma unroll
    for (int o = 16; o; o >>= 1) {
        s  += __shfl_xor_sync(0xffffffffu, s, o);
        s2 += __shfl_xor_sync(0xffffffffu, s2, o);
    }
    const int warp = tid >> 5, lane = tid & 31;
    if (lane == 0) { shs[warp] = s; shq[warp] = s2; }
    __syncthreads();
    if (tid < 32) {
        s  = (tid < 8) ? shs[tid] : 0.0f;
        s2 = (tid < 8) ? shq[tid] : 0.0f;
        #pragma unroll
        for (int o = 4; o; o >>= 1) {
            s  += __shfl_xor_sync(0xffffffffu, s, o);
            s2 += __shfl_xor_sync(0xffffffffu, s2, o);
        }
        if (tid == 0) { shs[0] = s; shq[0] = s2; }
    }
    __syncthreads();
    s = shs[0]; s2 = shq[0];

    const float mean = s * (1.0f / E);
    const float var  = s2 * (1.0f / E) - mean * mean;
    const float inv  = rsqrtf(var + EPS);
    const float g    = gamma[0];
    const float4 bt  = *reinterpret_cast<const float4*>(beta + tid * 4);

    float4 res;
    res.x = g * (v.x - mean) * inv + bt.x;
    res.y = g * (v.y - mean) * inv + bt.y;
    res.z = g * (v.z - mean) * inv + bt.z;
    res.w = g * (v.w - mean) * inv + bt.w;
    *reinterpret_cast<float4*>(out + (size_t)row * E + tid * 4) = res;

    if (WB) {
        *reinterpret_cast<uint2*>(&oh[(size_t)row * E + tid * 4]) =
            make_uint2(packh2(res.x, res.y), packh2(res.z, res.w));
    }
}

// ---------------- launch ----------------
extern "C" void kernel_launch(void* const* d_in, const int* in_sizes, int n_in,
                              void* d_out, int out_size)
{
    const float* x      = (const float*)d_in[0];
    const float* wq     = (const float*)d_in[1];
    const float* wk     = (const float*)d_in[2];
    const float* wv     = (const float*)d_in[3];
    const float* pool_w = (const float*)d_in[4];
    const float* l1_w   = (const float*)d_in[5];
    const float* l1_b   = (const float*)d_in[6];
    const float* l2_w   = (const float*)d_in[7];
    const float* l2_b   = (const float*)d_in[8];
    const float* gamma  = (const float*)d_in[9];
    const float* beta   = (const float*)d_in[10];
    float* out = (float*)d_out;

    __half *px, *pW, *ppw, *pw1, *pw2, *pc, *phh, *pf;
    float *pA, *pH, *pN;
    cudaGetSymbolAddress((void**)&px,  g_x);
    cudaGetSymbolAddress((void**)&pW,  g_W);
    cudaGetSymbolAddress((void**)&ppw, g_pw);
    cudaGetSymbolAddress((void**)&pw1, g_w1);
    cudaGetSymbolAddress((void**)&pw2, g_w2);
    cudaGetSymbolAddress((void**)&pc,  g_c);
    cudaGetSymbolAddress((void**)&phh, g_hh);
    cudaGetSymbolAddress((void**)&pf,  g_f);
    cudaGetSymbolAddress((void**)&pA,  g_attn);
    cudaGetSymbolAddress((void**)&pH,  g_h);
    cudaGetSymbolAddress((void**)&pN,  g_ffn);

    conv_h<<<(T * E / 4 + 255) / 256, 256>>>((const float4*)x,      (uint2*)px,  T * E / 4);
    conv_qkvw_h<<<(E * N_QKV / 2 + 255) / 256, 256>>>(wq, wk, wv);
    conv_h<<<(E * E / 4 + 255) / 256, 256>>>((const float4*)pool_w, (uint2*)ppw, E * E / 4);
    conv_h<<<(E * F / 4 + 255) / 256, 256>>>((const float4*)l1_w,   (uint2*)pw1, E * F / 4);
    conv_h<<<(F * E / 4 + 255) / 256, 256>>>((const float4*)l2_w,   (uint2*)pw2, F * E / 4);

    gemm_h16<2, 0><<<dim3(N_QKV / 128, T / 128), 256>>>(
        px, pW, nullptr, nullptr, nullptr, N_QKV, E);
    attn_tc<<<dim3(T / 64, H), 128>>>();
    gemm_h16<0, 0><<<dim3(E / 128, T / 128), 256>>>(
        pc, ppw, nullptr, pA, nullptr, E, E);
    ln_kernel<1><<<T, 256>>>(x, pA, gamma, beta, pH, phh);
    gemm_h16<1, 1><<<dim3(F / 128, T / 128), 256>>>(
        phh, pw1, l1_b, nullptr, pf, F, E);
    gemm_h16<0, 1><<<dim3(E / 128, T / 128), 256>>>(
        pf, pw2, l2_b, pN, nullptr, E, F);
    ln_kernel<0><<<T, 256>>>(pH, pN, gamma, beta, out, nullptr);
}

// round 17
// speedup vs baseline: 2.3579x; 1.2285x over previous
#include <cuda_runtime.h>
#include <cuda_fp16.h>
#include <cstdint>

#define T  2048
#define E  1024
#define H  16
#define Dh 64
#define F  4096
#define EPS 1e-5f
#define N_QKV 3072

// ---------------- scratch (all fp16 now) ----------------
__device__ __half g_Q[H * T * Dh];
__device__ __half g_K[H * T * Dh];
__device__ __half g_V[H * T * Dh];

__device__ __half g_x[T * E];            // x (A of QKV gemm)
__device__ __half g_W[E * N_QKV];        // gathered qkv weights [K=E][N=3072]
__device__ __half g_pw[E * E];           // pool_w  [K=E][N=E]
__device__ __half g_w1[E * F];           // l1_w    [K=E][N=F]
__device__ __half g_w2[F * E];           // l2_w    [K=F][N=E]
__device__ __half g_c[T * E];            // attention concat (A of pool)
__device__ __half g_hh[T * E];           // ln1 out (A of ffn1)
__device__ __half g_f[T * F];            // ffn1 out (A of ffn2)

__device__ float g_attn[T * E];
__device__ float g_h[T * E];
__device__ float g_ffn[T * E];

// ---------------- helpers ----------------
__device__ __forceinline__ uint32_t smem_u32(const void* p) {
    return (uint32_t)__cvta_generic_to_shared(p);
}
__device__ __forceinline__ uint32_t packh2(float a, float b) {
    __half2 h = __floats2half2_rn(a, b);
    return *reinterpret_cast<uint32_t*>(&h);
}
__device__ __forceinline__ void cp16(void* dst, const void* src) {
    asm volatile("cp.async.cg.shared.global [%0],[%1],16;" :: "r"(smem_u32(dst)), "l"(src));
}
__device__ __forceinline__ void cp_commit() {
    asm volatile("cp.async.commit_group;" ::: "memory");
}
__device__ __forceinline__ void cp_wait0() {
    asm volatile("cp.async.wait_group 0;" ::: "memory");
}
__device__ __forceinline__ void ldm_x4(uint32_t* r, uint32_t a) {
    asm volatile("ldmatrix.sync.aligned.m8n8.x4.shared.b16 {%0,%1,%2,%3},[%4];"
                 : "=r"(r[0]), "=r"(r[1]), "=r"(r[2]), "=r"(r[3]) : "r"(a));
}
__device__ __forceinline__ void ldm_x4t(uint32_t* r, uint32_t a) {
    asm volatile("ldmatrix.sync.aligned.m8n8.x4.trans.shared.b16 {%0,%1,%2,%3},[%4];"
                 : "=r"(r[0]), "=r"(r[1]), "=r"(r[2]), "=r"(r[3]) : "r"(a));
}
__device__ __forceinline__ void ldm_x2t(uint32_t& r0, uint32_t& r1, uint32_t a) {
    asm volatile("ldmatrix.sync.aligned.m8n8.x2.trans.shared.b16 {%0,%1},[%2];"
                 : "=r"(r0), "=r"(r1) : "r"(a));
}
// fp16 mma
__device__ __forceinline__ void mma16816h(float* d, const uint32_t* a, const uint32_t* b) {
    asm volatile(
        "mma.sync.aligned.m16n8k16.row.col.f32.f16.f16.f32 "
        "{%0,%1,%2,%3},{%4,%5,%6,%7},{%8,%9},{%0,%1,%2,%3};"
        : "+f"(d[0]), "+f"(d[1]), "+f"(d[2]), "+f"(d[3])
        : "r"(a[0]), "r"(a[1]), "r"(a[2]), "r"(a[3]), "r"(b[0]), "r"(b[1]));
}

// =====================================================================
// Conversion kernels (fp32 -> fp16)
// =====================================================================
__global__ void conv_h(const float4* __restrict__ src, uint2* __restrict__ dst, int n4)
{
    const int i = blockIdx.x * blockDim.x + threadIdx.x;
    if (i < n4) {
        const float4 v = src[i];
        dst[i] = make_uint2(packh2(v.x, v.y), packh2(v.z, v.w));
    }
}

// gather wq/wk/wv[h][e][d] -> g_W[e][which*1024 + head*64 + d] fp16
__global__ void conv_qkvw_h(const float* __restrict__ wq,
                            const float* __restrict__ wk,
                            const float* __restrict__ wv)
{
    const int i = blockIdx.x * blockDim.x + threadIdx.x;
    if (i >= E * N_QKV / 2) return;
    const int e = i / (N_QKV / 2);
    const int n = (i % (N_QKV / 2)) * 2;
    const int which = n >> 10, head = (n >> 6) & 15, d = n & 63;
    const float* w = (which == 0 ? wq : which == 1 ? wk : wv);
    const size_t base = ((size_t)head * E + e) * Dh + d;
    *reinterpret_cast<uint32_t*>(&g_W[(size_t)e * N_QKV + n]) = packh2(w[base], w[base + 1]);
}

// =====================================================================
// fp16 single-term GEMM: 128x128 tile, BK=32, register-staged double
// store (R4 skeleton), 256 thr (8 warps = 2m x 4n), 32 HMMA/tile.
// MODE 0: f32 out (+BIAS). MODE 1: bias+relu -> fp16 out.
// MODE 2: QKV scatter -> fp16 Q(scaled)/K/V.
// =====================================================================
template<int MODE, int BIAS>
__global__ void __launch_bounds__(256) gemm_h16(
    const __half* __restrict__ A, const __half* __restrict__ B,
    const float* __restrict__ bias, float* __restrict__ Cf,
    __half* __restrict__ Ch, int N, int K)
{
    __shared__ __align__(16) __half As[2][128][24];
    __shared__ __align__(16) __half Bs[2][16][136];

    const int tid  = threadIdx.x;
    const int lane = tid & 31;
    const int wid  = tid >> 5;
    const int wm   = wid >> 2;
    const int wn   = wid & 3;
    const int m0   = blockIdx.y * 128;
    const int n0   = blockIdx.x * 128;
    const int KT   = K >> 5;

    uint4 a_reg[2], b_reg[2];

    auto load_tile = [&](int kt) {
        const int k0 = kt << 5;
        #pragma unroll
        for (int i = 0; i < 2; ++i) {
            const int idx = tid + i * 256;
            const int row = idx >> 2, cc = (idx & 3) * 8;
            a_reg[i] = *reinterpret_cast<const uint4*>(A + (size_t)(m0 + row) * K + k0 + cc);
        }
        #pragma unroll
        for (int i = 0; i < 2; ++i) {
            const int idx = tid + i * 256;
            const int kr = idx >> 4, cc = (idx & 15) * 8;
            b_reg[i] = *reinterpret_cast<const uint4*>(B + (size_t)(k0 + kr) * N + n0 + cc);
        }
    };
    auto store_tile = [&]() {
        #pragma unroll
        for (int i = 0; i < 2; ++i) {
            const int idx = tid + i * 256;
            const int row = idx >> 2, cc = (idx & 3) * 8;
            const int slab = cc >> 4, kk = cc & 15;
            *reinterpret_cast<uint4*>(&As[slab][row][kk]) = a_reg[i];
        }
        #pragma unroll
        for (int i = 0; i < 2; ++i) {
            const int idx = tid + i * 256;
            const int kr = idx >> 4, cc = (idx & 15) * 8;
            const int slab = kr >> 4, r = kr & 15;
            *reinterpret_cast<uint4*>(&Bs[slab][r][cc]) = b_reg[i];
        }
    };

    float acc[4][4][4] = {};
    load_tile(0);
    store_tile();
    __syncthreads();

    const int ar = lane & 15;
    const int ac = (lane >> 4) * 8;

    for (int kt = 0; kt < KT; ++kt) {
        if (kt + 1 < KT) load_tile(kt + 1);

        #pragma unroll
        for (int slab = 0; slab < 2; ++slab) {
            uint32_t af[4][4], bf[4][2];
            #pragma unroll
            for (int mt = 0; mt < 4; ++mt)
                ldm_x4(af[mt], smem_u32(&As[slab][wm * 64 + mt * 16 + ar][ac]));
            #pragma unroll
            for (int nt = 0; nt < 4; ++nt)
                ldm_x2t(bf[nt][0], bf[nt][1], smem_u32(&Bs[slab][ar][wn * 32 + nt * 8]));
            #pragma unroll
            for (int mt = 0; mt < 4; ++mt)
                #pragma unroll
                for (int nt = 0; nt < 4; ++nt)
                    mma16816h(acc[mt][nt], af[mt], bf[nt]);
        }
        __syncthreads();
        if (kt + 1 < KT) {
            store_tile();
            __syncthreads();
        }
    }

    #pragma unroll
    for (int mt = 0; mt < 4; ++mt) {
        const int m = m0 + wm * 64 + mt * 16 + (lane >> 2);
        #pragma unroll
        for (int nt = 0; nt < 4; ++nt) {
            const int n = n0 + wn * 32 + nt * 8 + (lane & 3) * 2;
            float v0 = acc[mt][nt][0], v1 = acc[mt][nt][1];
            float v2 = acc[mt][nt][2], v3 = acc[mt][nt][3];
            if (BIAS) { v0 += bias[n]; v1 += bias[n + 1]; v2 += bias[n]; v3 += bias[n + 1]; }
            if (MODE == 0) {
                *reinterpret_cast<float2*>(Cf + (size_t)m * N + n)       = make_float2(v0, v1);
                *reinterpret_cast<float2*>(Cf + (size_t)(m + 8) * N + n) = make_float2(v2, v3);
            } else if (MODE == 1) {
                v0 = fmaxf(v0, 0.f); v1 = fmaxf(v1, 0.f);
                v2 = fmaxf(v2, 0.f); v3 = fmaxf(v3, 0.f);
                *reinterpret_cast<uint32_t*>(&Ch[(size_t)m * N + n])       = packh2(v0, v1);
                *reinterpret_cast<uint32_t*>(&Ch[(size_t)(m + 8) * N + n]) = packh2(v2, v3);
            } else {   // MODE 2: QKV scatter, Q pre-scaled by 0.125
                const int w2 = n >> 10, h2 = (n >> 6) & 15, d2 = n & 63;
                if (w2 == 0) { v0 *= 0.125f; v1 *= 0.125f; v2 *= 0.125f; v3 *= 0.125f; }
                __half* dst = (w2 == 0 ? g_Q : w2 == 1 ? g_K : g_V);
                const size_t o0 = ((size_t)h2 * T + m) * Dh + d2;
                const size_t o1 = ((size_t)h2 * T + m + 8) * Dh + d2;
                *reinterpret_cast<uint32_t*>(&dst[o0]) = packh2(v0, v1);
                *reinterpret_cast<uint32_t*>(&dst[o1]) = packh2(v2, v3);
            }
        }
    }
}

// =====================================================================
// fp16 single-term flash attention: block = 4 warps, 64 q-rows, 1 head.
// S = Q@K^T (1 MMA per fragment); P@V (1 MMA per fragment).
// =====================================================================
__global__ void __launch_bounds__(128) attn_tc()
{
    __shared__ __align__(16) __half K_s[64][72];
    __shared__ __align__(16) __half V_s[64][72];

    const int tid  = threadIdx.x;
    const int lane = tid & 31;
    const int wid  = tid >> 5;
    const int qb   = (int)(gridDim.x - 1 - blockIdx.x) * 64;  // longest first
    const int h    = blockIdx.y;
    const int mbase = qb + wid * 16;

    const __half* Qp = g_Q + (size_t)h * T * Dh;
    const __half* Kp = g_K + (size_t)h * T * Dh;
    const __half* Vp = g_V + (size_t)h * T * Dh;

    // stage Q tile through K_s, ldmatrix to regs
    #pragma unroll
    for (int i = 0; i < 4; ++i) {
        const int idx = tid + i * 128;
        const int r = idx >> 3, c8 = idx & 7;
        cp16(&K_s[r][c8 * 8], Qp + (size_t)(qb + r) * Dh + c8 * 8);
    }
    cp_commit(); cp_wait0();
    __syncthreads();

    uint32_t qf[4][4];
    #pragma unroll
    for (int ks = 0; ks < 4; ++ks) {
        const int r = wid * 16 + (lane & 15);
        const int c = ks * 16 + (lane >> 4) * 8;
        ldm_x4(qf[ks], smem_u32(&K_s[r][c]));
    }
    __syncthreads();

    float oacc[8][4] = {};
    float m0 = -1e30f, m1 = -1e30f, l0 = 0.f, l1 = 0.f;
    const int niter = qb / 64 + 1;

    for (int it = 0; it < niter; ++it) {
        const int kb = it * 64;

        #pragma unroll
        for (int i = 0; i < 4; ++i) {
            const int idx = tid + i * 128;
            const int r = idx >> 3, c8 = idx & 7;
            const size_t go = (size_t)(kb + r) * Dh + c8 * 8;
            cp16(&K_s[r][c8 * 8], Kp + go);
            cp16(&V_s[r][c8 * 8], Vp + go);
        }
        cp_commit(); cp_wait0();
        __syncthreads();

        // ---- S = Q @ K^T
        float sacc[8][4] = {};
        #pragma unroll
        for (int ks = 0; ks < 4; ++ks) {
            #pragma unroll
            for (int jp = 0; jp < 4; ++jp) {
                uint32_t bh[4];
                const int row = jp * 16 + (lane & 7) + ((lane >> 4) << 3);
                const int col = ks * 16 + (((lane >> 3) & 1) << 3);
                ldm_x4(bh, smem_u32(&K_s[row][col]));
                mma16816h(sacc[2 * jp],     qf[ks], bh);
                mma16816h(sacc[2 * jp + 1], qf[ks], bh + 2);
            }
        }

        // ---- causal mask
        if (kb + 63 > mbase) {
            const int row0 = mbase + (lane >> 2);
            const int row1 = row0 + 8;
            const int cb   = kb + ((lane & 3) << 1);
            #pragma unroll
            for (int nt = 0; nt < 8; ++nt) {
                const int c = cb + nt * 8;
                if (c     > row0) sacc[nt][0] = -1e30f;
                if (c + 1 > row0) sacc[nt][1] = -1e30f;
                if (c     > row1) sacc[nt][2] = -1e30f;
                if (c + 1 > row1) sacc[nt][3] = -1e30f;
            }
        }

        // ---- online softmax
        float t0 = -1e30f, t1 = -1e30f;
        #pragma unroll
        for (int nt = 0; nt < 8; ++nt) {
            t0 = fmaxf(t0, fmaxf(sacc[nt][0], sacc[nt][1]));
            t1 = fmaxf(t1, fmaxf(sacc[nt][2], sacc[nt][3]));
        }
        t0 = fmaxf(t0, __shfl_xor_sync(0xffffffffu, t0, 1));
        t0 = fmaxf(t0, __shfl_xor_sync(0xffffffffu, t0, 2));
        t1 = fmaxf(t1, __shfl_xor_sync(0xffffffffu, t1, 1));
        t1 = fmaxf(t1, __shfl_xor_sync(0xffffffffu, t1, 2));
        const float mn0 = fmaxf(m0, t0), mn1 = fmaxf(m1, t1);
        const float a0 = __expf(m0 - mn0), a1 = __expf(m1 - mn1);
        m0 = mn0; m1 = mn1;

        float sum0 = 0.f, sum1 = 0.f;
        #pragma unroll
        for (int nt = 0; nt < 8; ++nt) {
            sacc[nt][0] = __expf(sacc[nt][0] - mn0);
            sacc[nt][1] = __expf(sacc[nt][1] - mn0);
            sacc[nt][2] = __expf(sacc[nt][2] - mn1);
            sacc[nt][3] = __expf(sacc[nt][3] - mn1);
            sum0 += sacc[nt][0] + sacc[nt][1];
            sum1 += sacc[nt][2] + sacc[nt][3];
        }
        sum0 += __shfl_xor_sync(0xffffffffu, sum0, 1);
        sum0 += __shfl_xor_sync(0xffffffffu, sum0, 2);
        sum1 += __shfl_xor_sync(0xffffffffu, sum1, 1);
        sum1 += __shfl_xor_sync(0xffffffffu, sum1, 2);
        l0 = l0 * a0 + sum0;
        l1 = l1 * a1 + sum1;

        #pragma unroll
        for (int nt = 0; nt < 8; ++nt) {
            oacc[nt][0] *= a0; oacc[nt][1] *= a0;
            oacc[nt][2] *= a1; oacc[nt][3] *= a1;
        }

        // ---- pack P as fp16 A-fragments
        uint32_t pf[4][4];
        #pragma unroll
        for (int ks = 0; ks < 4; ++ks) {
            pf[ks][0] = packh2(sacc[2 * ks][0],     sacc[2 * ks][1]);
            pf[ks][1] = packh2(sacc[2 * ks][2],     sacc[2 * ks][3]);
            pf[ks][2] = packh2(sacc[2 * ks + 1][0], sacc[2 * ks + 1][1]);
            pf[ks][3] = packh2(sacc[2 * ks + 1][2], sacc[2 * ks + 1][3]);
        }

        // ---- O += P @ V
        #pragma unroll
        for (int ks = 0; ks < 4; ++ks) {
            #pragma unroll
            for (int jp = 0; jp < 4; ++jp) {
                uint32_t vh[4];
                const int row = ks * 16 + (lane & 15);
                const int col = jp * 16 + ((lane >> 4) << 3);
                ldm_x4t(vh, smem_u32(&V_s[row][col]));
                mma16816h(oacc[2 * jp],     pf[ks], vh);
                mma16816h(oacc[2 * jp + 1], pf[ks], vh + 2);
            }
        }
        __syncthreads();
    }

    // epilogue: fp16 concat
    const float i0 = 1.0f / l0, i1 = 1.0f / l1;
    const int r0 = mbase + (lane >> 2);
    const int cb = h * Dh + ((lane & 3) << 1);
    #pragma unroll
    for (int nt = 0; nt < 8; ++nt) {
        const int c = cb + nt * 8;
        *reinterpret_cast<uint32_t*>(&g_c[(size_t)r0 * E + c]) =
            packh2(oacc[nt][0] * i0, oacc[nt][1] * i0);
        *reinterpret_cast<uint32_t*>(&g_c[(size_t)(r0 + 8) * E + c]) =
            packh2(oacc[nt][2] * i1, oacc[nt][3] * i1);
    }
}

// =====================================================================
// residual + LayerNorm (optional fp16 output)
// =====================================================================
template<int WB>
__global__ void ln_kernel(const float* __restrict__ a, const float* __restrict__ b,
                          const float* __restrict__ gamma, const float* __restrict__ beta,
                          float* __restrict__ out, __half* __restrict__ oh)
{
    const int row = blockIdx.x;
    const int tid = threadIdx.x;

    const float4 va = *reinterpret_cast<const float4*>(a + (size_t)row * E + tid * 4);
    const float4 vb = *reinterpret_cast<const float4*>(b + (size_t)row * E + tid * 4);
    float4 v = make_float4(va.x + vb.x, va.y + vb.y, va.z + vb.z, va.w + vb.w);

    float s  = v.x + v.y + v.z + v.w;
    float s2 = v.x * v.x + v.y * v.y + v.z * v.z + v.w * v.w;

    __shared__ float shs[32], shq[32];
    #pragma unroll
    for (int o = 16; o; o >>= 1) {
        s  += __shfl_xor_sync(0xffffffffu, s, o);
        s2 += __shfl_xor_sync(0xffffffffu, s2, o);
    }
    const int warp = tid >> 5, lane = tid & 31;
    if (lane == 0) { shs[warp] = s; shq[warp] = s2; }
    __syncthreads();
    if (tid < 32) {
        s  = (tid < 8) ? shs[tid] : 0.0f;
        s2 = (tid < 8) ? shq[tid] : 0.0f;
        #pragma unroll
        for (int o = 4; o; o >>= 1) {
            s  += __shfl_xor_sync(0xffffffffu, s, o);
            s2 += __shfl_xor_sync(0xffffffffu, s2, o);
        }
        if (tid == 0) { shs[0] = s; shq[0] = s2; }
    }
    __syncthreads();
    s = shs[0]; s2 = shq[0];

    const float mean = s * (1.0f / E);
    const float var  = s2 * (1.0f / E) - mean * mean;
    const float inv  = rsqrtf(var + EPS);
    const float g    = gamma[0];
    const float4 bt  = *reinterpret_cast<const float4*>(beta + tid * 4);

    float4 res;
    res.x = g * (v.x - mean) * inv + bt.x;
    res.y = g * (v.y - mean) * inv + bt.y;
    res.z = g * (v.z - mean) * inv + bt.z;
    res.w = g * (v.w - mean) * inv + bt.w;
    *reinterpret_cast<float4*>(out + (size_t)row * E + tid * 4) = res;

    if (WB) {
        *reinterpret_cast<uint2*>(&oh[(size_t)row * E + tid * 4]) =
            make_uint2(packh2(res.x, res.y), packh2(res.z, res.w));
    }
}

// ---------------- launch ----------------
extern "C" void kernel_launch(void* const* d_in, const int* in_sizes, int n_in,
                              void* d_out, int out_size)
{
    const float* x      = (const float*)d_in[0];
    const float* wq     = (const float*)d_in[1];
    const float* wk     = (const float*)d_in[2];
    const float* wv     = (const float*)d_in[3];
    const float* pool_w = (const float*)d_in[4];
    const float* l1_w   = (const float*)d_in[5];
    const float* l1_b   = (const float*)d_in[6];
    const float* l2_w   = (const float*)d_in[7];
    const float* l2_b   = (const float*)d_in[8];
    const float* gamma  = (const float*)d_in[9];
    const float* beta   = (const float*)d_in[10];
    float* out = (float*)d_out;

    __half *px, *pW, *ppw, *pw1, *pw2, *pc, *phh, *pf;
    float *pA, *pH, *pN;
    cudaGetSymbolAddress((void**)&px,  g_x);
    cudaGetSymbolAddress((void**)&pW,  g_W);
    cudaGetSymbolAddress((void**)&ppw, g_pw);
    cudaGetSymbolAddress((void**)&pw1, g_w1);
    cudaGetSymbolAddress((void**)&pw2, g_w2);
    cudaGetSymbolAddress((void**)&pc,  g_c);
    cudaGetSymbolAddress((void**)&phh, g_hh);
    cudaGetSymbolAddress((void**)&pf,  g_f);
    cudaGetSymbolAddress((void**)&pA,  g_attn);
    cudaGetSymbolAddress((void**)&pH,  g_h);
    cudaGetSymbolAddress((void**)&pN,  g_ffn);

    conv_h<<<(T * E / 4 + 255) / 256, 256>>>((const float4*)x,      (uint2*)px,  T * E / 4);
    conv_qkvw_h<<<(E * N_QKV / 2 + 255) / 256, 256>>>(wq, wk, wv);
    conv_h<<<(E * E / 4 + 255) / 256, 256>>>((const float4*)pool_w, (uint2*)ppw, E * E / 4);
    conv_h<<<(E * F / 4 + 255) / 256, 256>>>((const float4*)l1_w,   (uint2*)pw1, E * F / 4);
    conv_h<<<(F * E / 4 + 255) / 256, 256>>>((const float4*)l2_w,   (uint2*)pw2, F * E / 4);

    gemm_h16<2, 0><<<dim3(N_QKV / 128, T / 128), 256>>>(
        px, pW, nullptr, nullptr, nullptr, N_QKV, E);
    attn_tc<<<dim3(T / 64, H), 128>>>();
    gemm_h16<0, 0><<<dim3(E / 128, T / 128), 256>>>(
        pc, ppw, nullptr, pA, nullptr, E, E);
    ln_kernel<1><<<T, 256>>>(x, pA, gamma, beta, pH, phh);
    gemm_h16<1, 1><<<dim3(F / 128, T / 128), 256>>>(
        phh, pw1, l1_b, nullptr, pf, F, E);
    gemm_h16<0, 1><<<dim3(E / 128, T / 128), 256>>>(
        pf, pw2, l2_b, pN, nullptr, E, F);
    ln_kernel<0><<<T, 256>>>(pH, pN, gamma, beta, out, nullptr);
}